// round 8
// baseline (speedup 1.0000x reference)
#include <cuda_runtime.h>
#include <cuda_bf16.h>

// SSIM loss, fully fused. (1,3,2048,2048) fp32, VALID 11-tap separable Gaussian
// (sigma=1.5). Output scalar fp32 = 1 - mean(ssim_map) over (3,2038,2038).
//
// v8 = exact v2 main compute (proven 104us) + reduction via 64 SPREAD
// fixed-point atomics (128B apart -> no LTS same-address serialization, which
// floored v5/v6/v7 at ~175us) + 1-warp finalize kernel (~4us).

#define H_DIM 2048
#define W_DIM 2048
#define OUT_DIM 2038
#define TILE 32
#define IN_TILE 42
#define NTHREADS 128
#define GRID_X 64
#define GRID_Y 64

// Normalized gaussian(sigma=1.5, size=11); sum == 1.0f.
#define W0 0.00102841f
#define W1 0.00759878f
#define W2 0.03600077f
#define W3 0.10936067f
#define W4 0.21300553f
#define W5 0.26601168f

#define FIXED_SCALE 16777216.0   // 2^24
#define NSLOTS 64
#define SLOT_STRIDE 16           // 16 ull = 128 bytes between slots

__device__ unsigned long long g_accum[NSLOTS * SLOT_STRIDE];  // zero-init

// 8 x 11-tap dot products over an 18-wide window; constant weights -> FFMA-imm.
__device__ __forceinline__ void conv11(const float* __restrict__ v,
                                       float* __restrict__ acc) {
    const float W[11] = {W0, W1, W2, W3, W4, W5, W4, W3, W2, W1, W0};
    #pragma unroll
    for (int j = 0; j < 8; ++j) {
        float a = W0 * v[j];
        #pragma unroll
        for (int t = 1; t < 11; ++t)
            a = fmaf(W[t], v[j + t], a);
        acc[j] = a;
    }
}

__global__ __launch_bounds__(NTHREADS)
void ssim_main_kernel(const float* __restrict__ xin, const float* __restrict__ yin) {
    __shared__ float sx[IN_TILE][43];    // conflict-free window loads
    __shared__ float sy[IN_TILE][43];
    __shared__ float hb[5][IN_TILE][33]; // conflict-free stores + vertical reads
    __shared__ float red[4];

    const int tid = threadIdx.x;
    const int gx0 = blockIdx.x * TILE;
    const int gy0 = blockIdx.y * TILE;
    const float* __restrict__ xp = xin + (size_t)blockIdx.z * (H_DIM * W_DIM);
    const float* __restrict__ yp = yin + (size_t)blockIdx.z * (H_DIM * W_DIM);

    // ---- Load 42x42 x,y tile (zero clamp at image edge) ----
    for (int i = tid; i < IN_TILE * IN_TILE; i += NTHREADS) {
        int r = i / IN_TILE;
        int c = i - r * IN_TILE;
        int gr = gy0 + r;
        int gc = gx0 + c;
        float xv = 0.0f, yv = 0.0f;
        if (gr < H_DIM && gc < W_DIM) {
            int idx = gr * W_DIM + gc;
            xv = __ldg(xp + idx);
            yv = __ldg(yp + idx);
        }
        sx[r][c] = xv;
        sy[r][c] = yv;
    }
    __syncthreads();

    // ---- Phase A: horizontal blur of 5 maps; 42 rows x 4 runs of 8 ----
    for (int task = tid; task < IN_TILE * 4; task += NTHREADS) {
        int r  = task >> 2;
        int c0 = (task & 3) << 3;
        float xw[18], yw[18], pw[18], acc[8];

        #pragma unroll
        for (int k = 0; k < 18; ++k) xw[k] = sx[r][c0 + k];
        conv11(xw, acc);
        #pragma unroll
        for (int j = 0; j < 8; ++j) hb[0][r][c0 + j] = acc[j];

        #pragma unroll
        for (int k = 0; k < 18; ++k) yw[k] = sy[r][c0 + k];
        conv11(yw, acc);
        #pragma unroll
        for (int j = 0; j < 8; ++j) hb[1][r][c0 + j] = acc[j];

        #pragma unroll
        for (int k = 0; k < 18; ++k) pw[k] = xw[k] * xw[k];
        conv11(pw, acc);
        #pragma unroll
        for (int j = 0; j < 8; ++j) hb[2][r][c0 + j] = acc[j];

        #pragma unroll
        for (int k = 0; k < 18; ++k) pw[k] = yw[k] * yw[k];
        conv11(pw, acc);
        #pragma unroll
        for (int j = 0; j < 8; ++j) hb[3][r][c0 + j] = acc[j];

        #pragma unroll
        for (int k = 0; k < 18; ++k) pw[k] = xw[k] * yw[k];
        conv11(pw, acc);
        #pragma unroll
        for (int j = 0; j < 8; ++j) hb[4][r][c0 + j] = acc[j];
    }
    __syncthreads();

    // ---- Phase B: vertical blur (8 rows/thread, 4 warps) + SSIM + reduce ----
    const int tx  = tid & 31;
    const int tg  = tid >> 5;
    const int oyb = tg << 3;

    float acc[5][8];
    #pragma unroll
    for (int m = 0; m < 5; ++m) {
        float v[18];
        #pragma unroll
        for (int k = 0; k < 18; ++k) v[k] = hb[m][oyb + k][tx];
        conv11(v, acc[m]);
    }

    const float C1 = 0.01f * 0.01f;
    const float C2 = 0.03f * 0.03f;
    float lsum = 0.0f;
    const int ox = gx0 + tx;
    #pragma unroll
    for (int j = 0; j < 8; ++j) {
        int oy = gy0 + oyb + j;
        if (oy < OUT_DIM && ox < OUT_DIM) {
            float mu1 = acc[0][j], mu2 = acc[1][j];
            float m11 = mu1 * mu1;
            float m22 = mu2 * mu2;
            float m12 = mu1 * mu2;
            float s1  = acc[2][j] - m11;
            float s2  = acc[3][j] - m22;
            float s12 = acc[4][j] - m12;
            float num = (2.0f * m12 + C1) * (2.0f * s12 + C2);
            float den = (m11 + m22 + C1) * (s1 + s2 + C2);
            lsum += __fdividef(num, den);
        }
    }

    #pragma unroll
    for (int off = 16; off > 0; off >>= 1)
        lsum += __shfl_down_sync(0xffffffffu, lsum, off);
    if (tx == 0) red[tg] = lsum;
    __syncthreads();
    if (tid == 0) {
        float bs = red[0] + red[1] + red[2] + red[3];
        // Fixed-point: integer adds commute -> replay-deterministic.
        unsigned long long q =
            (unsigned long long)__double2ll_rn((double)bs * FIXED_SCALE);
        int bid = (blockIdx.z * GRID_Y + blockIdx.y) * GRID_X + (int)blockIdx.x;
        atomicAdd(&g_accum[(bid & (NSLOTS - 1)) * SLOT_STRIDE], q);
    }
}

__global__ void ssim_final_kernel(float* __restrict__ out) {
    const int lane = threadIdx.x;            // 32 threads
    unsigned long long s = g_accum[lane * SLOT_STRIDE]
                         + g_accum[(lane + 32) * SLOT_STRIDE];
    // reset for next graph replay
    g_accum[lane * SLOT_STRIDE] = 0ull;
    g_accum[(lane + 32) * SLOT_STRIDE] = 0ull;
    #pragma unroll
    for (int off = 16; off > 0; off >>= 1)
        s += __shfl_down_sync(0xffffffffu, s, off);
    if (lane == 0) {
        double mean = ((double)s / FIXED_SCALE) /
                      (3.0 * (double)OUT_DIM * (double)OUT_DIM);
        out[0] = 1.0f - (float)mean;
    }
}

extern "C" void kernel_launch(void* const* d_in, const int* in_sizes, int n_in,
                              void* d_out, int out_size) {
    const float* pred = (const float*)d_in[0];
    const float* targ = (const float*)d_in[1];
    float* out = (float*)d_out;

    dim3 grid(GRID_X, GRID_Y, 3);
    ssim_main_kernel<<<grid, NTHREADS>>>(pred, targ);
    ssim_final_kernel<<<1, 32>>>(out);
}

// round 9
// speedup vs baseline: 1.6043x; 1.6043x over previous
#include <cuda_runtime.h>
#include <cuda_bf16.h>

// SSIM loss, fully fused. (1,3,2048,2048) fp32, VALID 11-tap separable Gaussian
// (sigma=1.5). Output scalar fp32 = 1 - mean(ssim_map) over (3,2038,2038).
//
// v9 = BYTE-EXACT v2 main kernel (117.2us best: 32x32 tile, 128 thr, strides
// 43/33, FFMA-imm convs, plain per-block float store epilogue — no atomics,
// no fp64 in the main kernel) + faster tail (float4 loads, fp32 partial sums
// in fixed order, double only for the final combine; bit-deterministic).

#define H_DIM 2048
#define W_DIM 2048
#define OUT_DIM 2038
#define TILE 32
#define IN_TILE 42
#define NTHREADS 128
#define GRID_X 64
#define GRID_Y 64
#define NBLOCKS (GRID_X * GRID_Y * 3)

// Normalized gaussian(sigma=1.5, size=11); sum == 1.0f exactly.
#define W0 0.00102841f
#define W1 0.00759878f
#define W2 0.03600077f
#define W3 0.10936067f
#define W4 0.21300553f
#define W5 0.26601168f

__device__ float g_partial[NBLOCKS];

// 11-tap dot products over an 18-wide window -> 8 outputs, all FFMA-imm.
__device__ __forceinline__ void conv11(const float* __restrict__ v,
                                       float* __restrict__ acc) {
    const float W[11] = {W0, W1, W2, W3, W4, W5, W4, W3, W2, W1, W0};
    #pragma unroll
    for (int j = 0; j < 8; ++j) {
        float a = W0 * v[j];
        #pragma unroll
        for (int t = 1; t < 11; ++t)
            a = fmaf(W[t], v[j + t], a);
        acc[j] = a;
    }
}

__global__ __launch_bounds__(NTHREADS)
void ssim_main_kernel(const float* __restrict__ xin, const float* __restrict__ yin) {
    __shared__ float sx[IN_TILE][43];   // stride 43: conflict-free window loads
    __shared__ float sy[IN_TILE][43];
    __shared__ float hb[5][IN_TILE][33]; // stride 33: conflict-free ST + vert LD
    __shared__ float red[4];

    const int tid = threadIdx.x;
    const int gx0 = blockIdx.x * TILE;
    const int gy0 = blockIdx.y * TILE;
    const float* __restrict__ xp = xin + (size_t)blockIdx.z * (H_DIM * W_DIM);
    const float* __restrict__ yp = yin + (size_t)blockIdx.z * (H_DIM * W_DIM);

    // ---- Load 42x42 x,y tile (zero clamp at image edge) ----
    #pragma unroll
    for (int i = tid; i < IN_TILE * IN_TILE; i += NTHREADS) {
        int r = i / IN_TILE;
        int c = i - r * IN_TILE;
        int gr = gy0 + r;
        int gc = gx0 + c;
        float xv = 0.0f, yv = 0.0f;
        if (gr < H_DIM && gc < W_DIM) {
            int idx = gr * W_DIM + gc;
            xv = __ldg(xp + idx);
            yv = __ldg(yp + idx);
        }
        sx[r][c] = xv;
        sy[r][c] = yv;
    }
    __syncthreads();

    // ---- Phase A: horizontal blur of 5 maps (x, y, xy, xx, yy) ----
    // 42 rows x 4 runs of 8 cols = 168 tasks.
    for (int task = tid; task < IN_TILE * 4; task += NTHREADS) {
        int r  = task >> 2;
        int c0 = (task & 3) << 3;
        float xw[18], yw[18], pw[18], acc[8];

        #pragma unroll
        for (int k = 0; k < 18; ++k) xw[k] = sx[r][c0 + k];
        conv11(xw, acc);
        #pragma unroll
        for (int j = 0; j < 8; ++j) hb[0][r][c0 + j] = acc[j];

        #pragma unroll
        for (int k = 0; k < 18; ++k) yw[k] = sy[r][c0 + k];
        conv11(yw, acc);
        #pragma unroll
        for (int j = 0; j < 8; ++j) hb[1][r][c0 + j] = acc[j];

        #pragma unroll
        for (int k = 0; k < 18; ++k) pw[k] = xw[k] * yw[k];
        conv11(pw, acc);
        #pragma unroll
        for (int j = 0; j < 8; ++j) hb[4][r][c0 + j] = acc[j];

        #pragma unroll
        for (int k = 0; k < 18; ++k) pw[k] = xw[k] * xw[k];
        conv11(pw, acc);
        #pragma unroll
        for (int j = 0; j < 8; ++j) hb[2][r][c0 + j] = acc[j];

        #pragma unroll
        for (int k = 0; k < 18; ++k) pw[k] = yw[k] * yw[k];
        conv11(pw, acc);
        #pragma unroll
        for (int j = 0; j < 8; ++j) hb[3][r][c0 + j] = acc[j];
    }
    __syncthreads();

    // ---- Phase B: vertical blur (sliding window) + SSIM + reduce ----
    const int tx  = tid & 31;          // output column
    const int tg  = tid >> 5;          // row-group 0..3 (8 output rows each)
    const int oyb = tg << 3;

    float acc[5][8];
    #pragma unroll
    for (int m = 0; m < 5; ++m) {
        float v[18];
        #pragma unroll
        for (int k = 0; k < 18; ++k) v[k] = hb[m][oyb + k][tx];
        conv11(v, acc[m]);
    }

    const float C1 = 0.01f * 0.01f;
    const float C2 = 0.03f * 0.03f;
    float lsum = 0.0f;
    const int ox = gx0 + tx;
    #pragma unroll
    for (int j = 0; j < 8; ++j) {
        int oy = gy0 + oyb + j;
        if (oy < OUT_DIM && ox < OUT_DIM) {
            float mu1 = acc[0][j], mu2 = acc[1][j];
            float m11 = mu1 * mu1;
            float m22 = mu2 * mu2;
            float m12 = mu1 * mu2;
            float s1  = acc[2][j] - m11;
            float s2  = acc[3][j] - m22;
            float s12 = acc[4][j] - m12;
            float num = (2.0f * m12 + C1) * (2.0f * s12 + C2);
            float den = (m11 + m22 + C1) * (s1 + s2 + C2);
            lsum += __fdividef(num, den);
        }
    }

    #pragma unroll
    for (int off = 16; off > 0; off >>= 1)
        lsum += __shfl_down_sync(0xffffffffu, lsum, off);
    if (tx == 0) red[tg] = lsum;
    __syncthreads();
    if (tid == 0) {
        int bid = (blockIdx.z * GRID_Y + blockIdx.y) * GRID_X + blockIdx.x;
        g_partial[bid] = red[0] + red[1] + red[2] + red[3];
    }
}

// Tail: 1024 threads; thread t owns 3 float4 chunks (fixed order -> the fp32
// sums and the shuffle tree are schedule-independent => replay-deterministic).
__global__ __launch_bounds__(1024)
void ssim_final_kernel(float* __restrict__ out) {
    __shared__ double s[32];
    const int t = threadIdx.x;
    const float4* p = reinterpret_cast<const float4*>(g_partial);  // 3072 float4
    float4 a = p[t];
    float4 b = p[t + 1024];
    float4 c = p[t + 2048];
    float fs = ((a.x + a.y) + (a.z + a.w))
             + ((b.x + b.y) + (b.z + b.w))
             + ((c.x + c.y) + (c.z + c.w));
    double sum = (double)fs;
    #pragma unroll
    for (int off = 16; off > 0; off >>= 1)
        sum += __shfl_down_sync(0xffffffffu, sum, off);
    int lane = t & 31, wid = t >> 5;
    if (lane == 0) s[wid] = sum;
    __syncthreads();
    if (wid == 0) {
        double v = s[lane];
        #pragma unroll
        for (int off = 16; off > 0; off >>= 1)
            v += __shfl_down_sync(0xffffffffu, v, off);
        if (lane == 0) {
            double n = 3.0 * (double)OUT_DIM * (double)OUT_DIM;
            out[0] = 1.0f - (float)(v / n);
        }
    }
}

extern "C" void kernel_launch(void* const* d_in, const int* in_sizes, int n_in,
                              void* d_out, int out_size) {
    const float* pred = (const float*)d_in[0];
    const float* targ = (const float*)d_in[1];
    float* out = (float*)d_out;

    dim3 grid(GRID_X, GRID_Y, 3);
    ssim_main_kernel<<<grid, NTHREADS>>>(pred, targ);
    ssim_final_kernel<<<1, 1024>>>(out);
}

// round 10
// speedup vs baseline: 2.0094x; 1.2525x over previous
#include <cuda_runtime.h>
#include <cuda_bf16.h>

// SSIM loss, fully fused. (1,3,2048,2048) fp32, VALID 11-tap separable Gaussian
// (sigma=1.5). Output scalar fp32 = 1 - mean(ssim_map) over (3,2038,2038).
//
// v10 = v9 (111.1us) with the sx/sy SMEM staging deleted: phase A reads its
// 18-float windows directly from gmem (__ldg float4, L1-cached halo overlap).
// smem 42.2KB -> 27.8KB, occupancy 5 -> 6 CTAs/SM. Phase B + epilogue + tail
// byte-identical to v9 (proven).

#define H_DIM 2048
#define W_DIM 2048
#define OUT_DIM 2038
#define TILE 32
#define IN_TILE 42
#define NTHREADS 128
#define GRID_X 64
#define GRID_Y 64
#define NBLOCKS (GRID_X * GRID_Y * 3)

// Normalized gaussian(sigma=1.5, size=11); sum == 1.0f exactly.
#define W0 0.00102841f
#define W1 0.00759878f
#define W2 0.03600077f
#define W3 0.10936067f
#define W4 0.21300553f
#define W5 0.26601168f

__device__ float g_partial[NBLOCKS];

// 11-tap dot products over an 18-wide window -> 8 outputs, all FFMA-imm.
__device__ __forceinline__ void conv11(const float* __restrict__ v,
                                       float* __restrict__ acc) {
    const float W[11] = {W0, W1, W2, W3, W4, W5, W4, W3, W2, W1, W0};
    #pragma unroll
    for (int j = 0; j < 8; ++j) {
        float a = W0 * v[j];
        #pragma unroll
        for (int t = 1; t < 11; ++t)
            a = fmaf(W[t], v[j + t], a);
        acc[j] = a;
    }
}

__device__ __forceinline__ void load18(const float* __restrict__ p,
                                       float* __restrict__ v) {
    // p is 32B-aligned (offset multiple of 8 floats). 4xLDG.128 + 1xLDG.64.
    #pragma unroll
    for (int k = 0; k < 4; ++k) {
        float4 q = __ldg(reinterpret_cast<const float4*>(p) + k);
        v[4 * k + 0] = q.x; v[4 * k + 1] = q.y;
        v[4 * k + 2] = q.z; v[4 * k + 3] = q.w;
    }
    float2 q2 = __ldg(reinterpret_cast<const float2*>(p) + 8);
    v[16] = q2.x; v[17] = q2.y;
}

__global__ __launch_bounds__(NTHREADS, 6)
void ssim_main_kernel(const float* __restrict__ xin, const float* __restrict__ yin) {
    __shared__ float hb[5][IN_TILE][33];  // stride 33: conflict-free ST + vert LD
    __shared__ float red[4];

    const int tid = threadIdx.x;
    const int gx0 = blockIdx.x * TILE;
    const int gy0 = blockIdx.y * TILE;
    const float* __restrict__ xp = xin + (size_t)blockIdx.z * (H_DIM * W_DIM);
    const float* __restrict__ yp = yin + (size_t)blockIdx.z * (H_DIM * W_DIM);
    const bool interior = (blockIdx.x < GRID_X - 1) && (blockIdx.y < GRID_Y - 1);

    // ---- Phase A: horizontal blur of 5 maps (x, y, xy, xx, yy) ----
    // 42 rows x 4 runs of 8 cols = 168 tasks; windows read straight from gmem.
    for (int task = tid; task < IN_TILE * 4; task += NTHREADS) {
        int r  = task >> 2;
        int c0 = (task & 3) << 3;
        int gr = gy0 + r;
        int gc0 = gx0 + c0;
        float xw[18], yw[18], pw[18], acc[8];

        if (interior) {
            const float* xr = xp + (size_t)gr * W_DIM + gc0;
            const float* yr = yp + (size_t)gr * W_DIM + gc0;
            load18(xr, xw);
            load18(yr, yw);
        } else {
            #pragma unroll
            for (int k = 0; k < 18; ++k) {
                int gc = gc0 + k;
                bool ok = (gr < H_DIM) && (gc < W_DIM);
                int idx = gr * W_DIM + gc;
                xw[k] = ok ? __ldg(xp + idx) : 0.0f;
                yw[k] = ok ? __ldg(yp + idx) : 0.0f;
            }
        }

        conv11(xw, acc);
        #pragma unroll
        for (int j = 0; j < 8; ++j) hb[0][r][c0 + j] = acc[j];

        conv11(yw, acc);
        #pragma unroll
        for (int j = 0; j < 8; ++j) hb[1][r][c0 + j] = acc[j];

        #pragma unroll
        for (int k = 0; k < 18; ++k) pw[k] = xw[k] * yw[k];
        conv11(pw, acc);
        #pragma unroll
        for (int j = 0; j < 8; ++j) hb[4][r][c0 + j] = acc[j];

        #pragma unroll
        for (int k = 0; k < 18; ++k) pw[k] = xw[k] * xw[k];
        conv11(pw, acc);
        #pragma unroll
        for (int j = 0; j < 8; ++j) hb[2][r][c0 + j] = acc[j];

        #pragma unroll
        for (int k = 0; k < 18; ++k) pw[k] = yw[k] * yw[k];
        conv11(pw, acc);
        #pragma unroll
        for (int j = 0; j < 8; ++j) hb[3][r][c0 + j] = acc[j];
    }
    __syncthreads();

    // ---- Phase B: vertical blur (8 rows/thread, 4 warps) + SSIM + reduce ----
    const int tx  = tid & 31;          // output column
    const int tg  = tid >> 5;          // row-group 0..3 (8 output rows each)
    const int oyb = tg << 3;

    float acc[5][8];
    #pragma unroll
    for (int m = 0; m < 5; ++m) {
        float v[18];
        #pragma unroll
        for (int k = 0; k < 18; ++k) v[k] = hb[m][oyb + k][tx];
        conv11(v, acc[m]);
    }

    const float C1 = 0.01f * 0.01f;
    const float C2 = 0.03f * 0.03f;
    float lsum = 0.0f;
    const int ox = gx0 + tx;
    #pragma unroll
    for (int j = 0; j < 8; ++j) {
        int oy = gy0 + oyb + j;
        if (oy < OUT_DIM && ox < OUT_DIM) {
            float mu1 = acc[0][j], mu2 = acc[1][j];
            float m11 = mu1 * mu1;
            float m22 = mu2 * mu2;
            float m12 = mu1 * mu2;
            float s1  = acc[2][j] - m11;
            float s2  = acc[3][j] - m22;
            float s12 = acc[4][j] - m12;
            float num = (2.0f * m12 + C1) * (2.0f * s12 + C2);
            float den = (m11 + m22 + C1) * (s1 + s2 + C2);
            lsum += __fdividef(num, den);
        }
    }

    #pragma unroll
    for (int off = 16; off > 0; off >>= 1)
        lsum += __shfl_down_sync(0xffffffffu, lsum, off);
    if (tx == 0) red[tg] = lsum;
    __syncthreads();
    if (tid == 0) {
        int bid = (blockIdx.z * GRID_Y + blockIdx.y) * GRID_X + blockIdx.x;
        g_partial[bid] = red[0] + red[1] + red[2] + red[3];
    }
}

// Tail: 1024 threads; fixed-order fp32 partial sums + shuffle tree -> replay-
// deterministic; double only for the final combine.
__global__ __launch_bounds__(1024)
void ssim_final_kernel(float* __restrict__ out) {
    __shared__ double s[32];
    const int t = threadIdx.x;
    const float4* p = reinterpret_cast<const float4*>(g_partial);  // 3072 float4
    float4 a = p[t];
    float4 b = p[t + 1024];
    float4 c = p[t + 2048];
    float fs = ((a.x + a.y) + (a.z + a.w))
             + ((b.x + b.y) + (b.z + b.w))
             + ((c.x + c.y) + (c.z + c.w));
    double sum = (double)fs;
    #pragma unroll
    for (int off = 16; off > 0; off >>= 1)
        sum += __shfl_down_sync(0xffffffffu, sum, off);
    int lane = t & 31, wid = t >> 5;
    if (lane == 0) s[wid] = sum;
    __syncthreads();
    if (wid == 0) {
        double v = s[lane];
        #pragma unroll
        for (int off = 16; off > 0; off >>= 1)
            v += __shfl_down_sync(0xffffffffu, v, off);
        if (lane == 0) {
            double n = 3.0 * (double)OUT_DIM * (double)OUT_DIM;
            out[0] = 1.0f - (float)(v / n);
        }
    }
}

extern "C" void kernel_launch(void* const* d_in, const int* in_sizes, int n_in,
                              void* d_out, int out_size) {
    const float* pred = (const float*)d_in[0];
    const float* targ = (const float*)d_in[1];
    float* out = (float*)d_out;

    dim3 grid(GRID_X, GRID_Y, 3);
    ssim_main_kernel<<<grid, NTHREADS>>>(pred, targ);
    ssim_final_kernel<<<1, 1024>>>(out);
}

// round 11
// speedup vs baseline: 2.3286x; 1.1589x over previous
#include <cuda_runtime.h>
#include <cuda_bf16.h>

// SSIM loss, fully fused. (1,3,2048,2048) fp32, VALID 11-tap separable Gaussian
// (sigma=1.5). Output scalar fp32 = 1 - mean(ssim_map) over (3,2038,2038).
//
// v11 = v10 (88.7us) with 5 blur maps reduced to 4 via linearity:
//   P = blur((x+y)^2), Q = blur((x-y)^2)
//   E[xy] = (P-Q)/4,  E[x^2]+E[y^2] = (P+Q)/2
// -20% conv FMAs in both phases, -20% hb smem traffic, smem 27.8->22.5KB.

#define H_DIM 2048
#define W_DIM 2048
#define OUT_DIM 2038
#define TILE 32
#define IN_TILE 42
#define NTHREADS 128
#define GRID_X 64
#define GRID_Y 64
#define NBLOCKS (GRID_X * GRID_Y * 3)

// Normalized gaussian(sigma=1.5, size=11); sum == 1.0f exactly.
#define W0 0.00102841f
#define W1 0.00759878f
#define W2 0.03600077f
#define W3 0.10936067f
#define W4 0.21300553f
#define W5 0.26601168f

__device__ float g_partial[NBLOCKS];

// 11-tap dot products over an 18-wide window -> 8 outputs, all FFMA-imm.
__device__ __forceinline__ void conv11(const float* __restrict__ v,
                                       float* __restrict__ acc) {
    const float W[11] = {W0, W1, W2, W3, W4, W5, W4, W3, W2, W1, W0};
    #pragma unroll
    for (int j = 0; j < 8; ++j) {
        float a = W0 * v[j];
        #pragma unroll
        for (int t = 1; t < 11; ++t)
            a = fmaf(W[t], v[j + t], a);
        acc[j] = a;
    }
}

__device__ __forceinline__ void load18(const float* __restrict__ p,
                                       float* __restrict__ v) {
    // p is 32B-aligned (offset multiple of 8 floats). 4xLDG.128 + 1xLDG.64.
    #pragma unroll
    for (int k = 0; k < 4; ++k) {
        float4 q = __ldg(reinterpret_cast<const float4*>(p) + k);
        v[4 * k + 0] = q.x; v[4 * k + 1] = q.y;
        v[4 * k + 2] = q.z; v[4 * k + 3] = q.w;
    }
    float2 q2 = __ldg(reinterpret_cast<const float2*>(p) + 8);
    v[16] = q2.x; v[17] = q2.y;
}

__global__ __launch_bounds__(NTHREADS, 6)
void ssim_main_kernel(const float* __restrict__ xin, const float* __restrict__ yin) {
    __shared__ float hb[4][IN_TILE][33];  // stride 33: conflict-free ST + vert LD
    __shared__ float red[4];

    const int tid = threadIdx.x;
    const int gx0 = blockIdx.x * TILE;
    const int gy0 = blockIdx.y * TILE;
    const float* __restrict__ xp = xin + (size_t)blockIdx.z * (H_DIM * W_DIM);
    const float* __restrict__ yp = yin + (size_t)blockIdx.z * (H_DIM * W_DIM);
    const bool interior = (blockIdx.x < GRID_X - 1) && (blockIdx.y < GRID_Y - 1);

    // ---- Phase A: horizontal blur of 4 maps (x, y, (x+y)^2, (x-y)^2) ----
    // 42 rows x 4 runs of 8 cols = 168 tasks; windows read straight from gmem.
    for (int task = tid; task < IN_TILE * 4; task += NTHREADS) {
        int r  = task >> 2;
        int c0 = (task & 3) << 3;
        int gr = gy0 + r;
        int gc0 = gx0 + c0;
        float xw[18], yw[18], pw[18], acc[8];

        if (interior) {
            const float* xr = xp + (size_t)gr * W_DIM + gc0;
            const float* yr = yp + (size_t)gr * W_DIM + gc0;
            load18(xr, xw);
            load18(yr, yw);
        } else {
            #pragma unroll
            for (int k = 0; k < 18; ++k) {
                int gc = gc0 + k;
                bool ok = (gr < H_DIM) && (gc < W_DIM);
                int idx = gr * W_DIM + gc;
                xw[k] = ok ? __ldg(xp + idx) : 0.0f;
                yw[k] = ok ? __ldg(yp + idx) : 0.0f;
            }
        }

        conv11(xw, acc);
        #pragma unroll
        for (int j = 0; j < 8; ++j) hb[0][r][c0 + j] = acc[j];

        conv11(yw, acc);
        #pragma unroll
        for (int j = 0; j < 8; ++j) hb[1][r][c0 + j] = acc[j];

        #pragma unroll
        for (int k = 0; k < 18; ++k) {
            float u = xw[k] + yw[k];
            pw[k] = u * u;
        }
        conv11(pw, acc);
        #pragma unroll
        for (int j = 0; j < 8; ++j) hb[2][r][c0 + j] = acc[j];

        #pragma unroll
        for (int k = 0; k < 18; ++k) {
            float d = xw[k] - yw[k];
            pw[k] = d * d;
        }
        conv11(pw, acc);
        #pragma unroll
        for (int j = 0; j < 8; ++j) hb[3][r][c0 + j] = acc[j];
    }
    __syncthreads();

    // ---- Phase B: vertical blur (8 rows/thread, 4 warps) + SSIM + reduce ----
    const int tx  = tid & 31;          // output column
    const int tg  = tid >> 5;          // row-group 0..3 (8 output rows each)
    const int oyb = tg << 3;

    float acc[4][8];
    #pragma unroll
    for (int m = 0; m < 4; ++m) {
        float v[18];
        #pragma unroll
        for (int k = 0; k < 18; ++k) v[k] = hb[m][oyb + k][tx];
        conv11(v, acc[m]);
    }

    const float C1 = 0.01f * 0.01f;
    const float C2 = 0.03f * 0.03f;
    float lsum = 0.0f;
    const int ox = gx0 + tx;
    #pragma unroll
    for (int j = 0; j < 8; ++j) {
        int oy = gy0 + oyb + j;
        if (oy < OUT_DIM && ox < OUT_DIM) {
            float mu1 = acc[0][j], mu2 = acc[1][j];
            float P   = acc[2][j], Q   = acc[3][j];
            float m11 = mu1 * mu1;
            float m22 = mu2 * mu2;
            float m12 = mu1 * mu2;
            // 2*sigma12 = 0.5*(P-Q) - 2*m12 ; sigma1_sq+sigma2_sq = 0.5*(P+Q) - m11 - m22
            float num = (2.0f * m12 + C1) * (0.5f * (P - Q) - 2.0f * m12 + C2);
            float den = (m11 + m22 + C1) * (0.5f * (P + Q) - m11 - m22 + C2);
            lsum += __fdividef(num, den);
        }
    }

    #pragma unroll
    for (int off = 16; off > 0; off >>= 1)
        lsum += __shfl_down_sync(0xffffffffu, lsum, off);
    if (tx == 0) red[tg] = lsum;
    __syncthreads();
    if (tid == 0) {
        int bid = (blockIdx.z * GRID_Y + blockIdx.y) * GRID_X + blockIdx.x;
        g_partial[bid] = red[0] + red[1] + red[2] + red[3];
    }
}

// Tail: 1024 threads; fixed-order fp32 partial sums + shuffle tree -> replay-
// deterministic; double only for the final combine.
__global__ __launch_bounds__(1024)
void ssim_final_kernel(float* __restrict__ out) {
    __shared__ double s[32];
    const int t = threadIdx.x;
    const float4* p = reinterpret_cast<const float4*>(g_partial);  // 3072 float4
    float4 a = p[t];
    float4 b = p[t + 1024];
    float4 c = p[t + 2048];
    float fs = ((a.x + a.y) + (a.z + a.w))
             + ((b.x + b.y) + (b.z + b.w))
             + ((c.x + c.y) + (c.z + c.w));
    double sum = (double)fs;
    #pragma unroll
    for (int off = 16; off > 0; off >>= 1)
        sum += __shfl_down_sync(0xffffffffu, sum, off);
    int lane = t & 31, wid = t >> 5;
    if (lane == 0) s[wid] = sum;
    __syncthreads();
    if (wid == 0) {
        double v = s[lane];
        #pragma unroll
        for (int off = 16; off > 0; off >>= 1)
            v += __shfl_down_sync(0xffffffffu, v, off);
        if (lane == 0) {
            double n = 3.0 * (double)OUT_DIM * (double)OUT_DIM;
            out[0] = 1.0f - (float)(v / n);
        }
    }
}

extern "C" void kernel_launch(void* const* d_in, const int* in_sizes, int n_in,
                              void* d_out, int out_size) {
    const float* pred = (const float*)d_in[0];
    const float* targ = (const float*)d_in[1];
    float* out = (float*)d_out;

    dim3 grid(GRID_X, GRID_Y, 3);
    ssim_main_kernel<<<grid, NTHREADS>>>(pred, targ);
    ssim_final_kernel<<<1, 1024>>>(out);
}

// round 12
// speedup vs baseline: 2.3502x; 1.0093x over previous
#include <cuda_runtime.h>
#include <cuda_bf16.h>

// SSIM loss, fully fused. (1,3,2048,2048) fp32, VALID 11-tap separable Gaussian
// (sigma=1.5). Output scalar fp32 = 1 - mean(ssim_map) over (3,2038,2038).
//
// v12 = v11 (76.5us) + two occupancy/issue levers:
//  - __launch_bounds__(128, 7): 73-reg cap -> 7 CTAs/SM (28 warps, +17%)
//  - HB_STRIDE 33 -> 36: 16B-aligned hb rows -> STS.128 stores (32 -> 8 store
//    instr per task); store/load patterns verified conflict-free mod 32.

#define H_DIM 2048
#define W_DIM 2048
#define OUT_DIM 2038
#define TILE 32
#define IN_TILE 42
#define NTHREADS 128
#define HB_STRIDE 36
#define GRID_X 64
#define GRID_Y 64
#define NBLOCKS (GRID_X * GRID_Y * 3)

// Normalized gaussian(sigma=1.5, size=11); sum == 1.0f exactly.
#define W0 0.00102841f
#define W1 0.00759878f
#define W2 0.03600077f
#define W3 0.10936067f
#define W4 0.21300553f
#define W5 0.26601168f

__device__ float g_partial[NBLOCKS];

// 11-tap dot products over an 18-wide window -> 8 outputs, all FFMA-imm.
__device__ __forceinline__ void conv11(const float* __restrict__ v,
                                       float* __restrict__ acc) {
    const float W[11] = {W0, W1, W2, W3, W4, W5, W4, W3, W2, W1, W0};
    #pragma unroll
    for (int j = 0; j < 8; ++j) {
        float a = W0 * v[j];
        #pragma unroll
        for (int t = 1; t < 11; ++t)
            a = fmaf(W[t], v[j + t], a);
        acc[j] = a;
    }
}

__device__ __forceinline__ void load18(const float* __restrict__ p,
                                       float* __restrict__ v) {
    // p is 32B-aligned (offset multiple of 8 floats). 4xLDG.128 + 1xLDG.64.
    #pragma unroll
    for (int k = 0; k < 4; ++k) {
        float4 q = __ldg(reinterpret_cast<const float4*>(p) + k);
        v[4 * k + 0] = q.x; v[4 * k + 1] = q.y;
        v[4 * k + 2] = q.z; v[4 * k + 3] = q.w;
    }
    float2 q2 = __ldg(reinterpret_cast<const float2*>(p) + 8);
    v[16] = q2.x; v[17] = q2.y;
}

__device__ __forceinline__ void store8(float* __restrict__ dst,
                                       const float* __restrict__ a) {
    // dst is 16B-aligned (row*36 and c0 both multiples of 4 floats).
    float4* d4 = reinterpret_cast<float4*>(dst);
    d4[0] = make_float4(a[0], a[1], a[2], a[3]);
    d4[1] = make_float4(a[4], a[5], a[6], a[7]);
}

__global__ __launch_bounds__(NTHREADS, 7)
void ssim_main_kernel(const float* __restrict__ xin, const float* __restrict__ yin) {
    __shared__ float hb[4][IN_TILE][HB_STRIDE];
    __shared__ float red[4];

    const int tid = threadIdx.x;
    const int gx0 = blockIdx.x * TILE;
    const int gy0 = blockIdx.y * TILE;
    const float* __restrict__ xp = xin + (size_t)blockIdx.z * (H_DIM * W_DIM);
    const float* __restrict__ yp = yin + (size_t)blockIdx.z * (H_DIM * W_DIM);
    const bool interior = (blockIdx.x < GRID_X - 1) && (blockIdx.y < GRID_Y - 1);

    // ---- Phase A: horizontal blur of 4 maps (x, y, (x+y)^2, (x-y)^2) ----
    // 42 rows x 4 runs of 8 cols = 168 tasks; windows read straight from gmem.
    for (int task = tid; task < IN_TILE * 4; task += NTHREADS) {
        int r  = task >> 2;
        int c0 = (task & 3) << 3;
        int gr = gy0 + r;
        int gc0 = gx0 + c0;
        float xw[18], yw[18], pw[18], acc[8];

        if (interior) {
            const float* xr = xp + (size_t)gr * W_DIM + gc0;
            const float* yr = yp + (size_t)gr * W_DIM + gc0;
            load18(xr, xw);
            load18(yr, yw);
        } else {
            #pragma unroll
            for (int k = 0; k < 18; ++k) {
                int gc = gc0 + k;
                bool ok = (gr < H_DIM) && (gc < W_DIM);
                int idx = gr * W_DIM + gc;
                xw[k] = ok ? __ldg(xp + idx) : 0.0f;
                yw[k] = ok ? __ldg(yp + idx) : 0.0f;
            }
        }

        conv11(xw, acc);
        store8(&hb[0][r][c0], acc);

        conv11(yw, acc);
        store8(&hb[1][r][c0], acc);

        #pragma unroll
        for (int k = 0; k < 18; ++k) {
            float u = xw[k] + yw[k];
            pw[k] = u * u;
        }
        conv11(pw, acc);
        store8(&hb[2][r][c0], acc);

        #pragma unroll
        for (int k = 0; k < 18; ++k) {
            float d = xw[k] - yw[k];
            pw[k] = d * d;
        }
        conv11(pw, acc);
        store8(&hb[3][r][c0], acc);
    }
    __syncthreads();

    // ---- Phase B: vertical blur (8 rows/thread, 4 warps) + SSIM + reduce ----
    const int tx  = tid & 31;          // output column
    const int tg  = tid >> 5;          // row-group 0..3 (8 output rows each)
    const int oyb = tg << 3;

    float acc[4][8];
    #pragma unroll
    for (int m = 0; m < 4; ++m) {
        float v[18];
        #pragma unroll
        for (int k = 0; k < 18; ++k) v[k] = hb[m][oyb + k][tx];
        conv11(v, acc[m]);
    }

    const float C1 = 0.01f * 0.01f;
    const float C2 = 0.03f * 0.03f;
    float lsum = 0.0f;
    const int ox = gx0 + tx;
    #pragma unroll
    for (int j = 0; j < 8; ++j) {
        int oy = gy0 + oyb + j;
        if (oy < OUT_DIM && ox < OUT_DIM) {
            float mu1 = acc[0][j], mu2 = acc[1][j];
            float P   = acc[2][j], Q   = acc[3][j];
            float m11 = mu1 * mu1;
            float m22 = mu2 * mu2;
            float m12 = mu1 * mu2;
            // 2*sigma12 = 0.5*(P-Q) - 2*m12 ; sigma1+sigma2 = 0.5*(P+Q) - m11 - m22
            float num = (2.0f * m12 + C1) * (0.5f * (P - Q) - 2.0f * m12 + C2);
            float den = (m11 + m22 + C1) * (0.5f * (P + Q) - m11 - m22 + C2);
            lsum += __fdividef(num, den);
        }
    }

    #pragma unroll
    for (int off = 16; off > 0; off >>= 1)
        lsum += __shfl_down_sync(0xffffffffu, lsum, off);
    if (tx == 0) red[tg] = lsum;
    __syncthreads();
    if (tid == 0) {
        int bid = (blockIdx.z * GRID_Y + blockIdx.y) * GRID_X + blockIdx.x;
        g_partial[bid] = red[0] + red[1] + red[2] + red[3];
    }
}

// Tail: 1024 threads; fixed-order fp32 partial sums + shuffle tree -> replay-
// deterministic; double only for the final combine.
__global__ __launch_bounds__(1024)
void ssim_final_kernel(float* __restrict__ out) {
    __shared__ double s[32];
    const int t = threadIdx.x;
    const float4* p = reinterpret_cast<const float4*>(g_partial);  // 3072 float4
    float4 a = p[t];
    float4 b = p[t + 1024];
    float4 c = p[t + 2048];
    float fs = ((a.x + a.y) + (a.z + a.w))
             + ((b.x + b.y) + (b.z + b.w))
             + ((c.x + c.y) + (c.z + c.w));
    double sum = (double)fs;
    #pragma unroll
    for (int off = 16; off > 0; off >>= 1)
        sum += __shfl_down_sync(0xffffffffu, sum, off);
    int lane = t & 31, wid = t >> 5;
    if (lane == 0) s[wid] = sum;
    __syncthreads();
    if (wid == 0) {
        double v = s[lane];
        #pragma unroll
        for (int off = 16; off > 0; off >>= 1)
            v += __shfl_down_sync(0xffffffffu, v, off);
        if (lane == 0) {
            double n = 3.0 * (double)OUT_DIM * (double)OUT_DIM;
            out[0] = 1.0f - (float)(v / n);
        }
    }
}

extern "C" void kernel_launch(void* const* d_in, const int* in_sizes, int n_in,
                              void* d_out, int out_size) {
    const float* pred = (const float*)d_in[0];
    const float* targ = (const float*)d_in[1];
    float* out = (float*)d_out;

    dim3 grid(GRID_X, GRID_Y, 3);
    ssim_main_kernel<<<grid, NTHREADS>>>(pred, targ);
    ssim_final_kernel<<<1, 1024>>>(out);
}